// round 16
// baseline (speedup 1.0000x reference)
#include <cuda_runtime.h>
#include <cstdint>

#define B_   16
#define Q_   900
#define C_   91
#define T_   100
#define BT_  1600
#define BQ_  14400
#define COST_ELEMS 23040000
#define RPB  4
#define CT   256
#define TILES (BQ_ / RPB)        // 3600

#define NB_A 57                  // tracked-column blocks (one row/thread)
#define NB_G 16                  // greedy blocks (one per batch)
#define NB_B 519                 // pure cost blocks
#define GRID (NB_A + NB_G + NB_B)   // 592 = exactly resident at 4 CTAs/SM

// dynamic smem layout (cost staging)
#define OFF_TB 0                         // float4[1600] target cxcywh
#define OFF_TL 25600                     // uchar[1600] labels
#define OFF_PR 27232                     // float[RPB][92] sigmoid probs
#define SMEM_DYN (OFF_PR + RPB * 92 * 4) // ~28.7 KB

// Transposed tracked columns: g_costT[b][col][row]; fully overwritten by A
// every run (no init needed). Contiguous columns for greedy reads.
__device__ float g_costT[B_][T_][Q_];
__device__ unsigned g_ready;    // zero-init; reset by last greedy block
__device__ unsigned g_done;     // zero-init; reset by last greedy block
__device__ unsigned g_tile;     // zero-init; work-steal counter, reset by last exiter
__device__ unsigned g_exit;     // zero-init; exit counter, reset by last exiter

__device__ __forceinline__ unsigned fkey(float f) {
    unsigned b = __float_as_uint(f);
    return (b & 0x80000000u) ? ~b : (b | 0x80000000u);
}
__device__ __forceinline__ unsigned redux_min_u32(unsigned v) {
    unsigned d;
    asm("redux.sync.min.u32 %0, %1, 0xffffffff;" : "=r"(d) : "r"(v));
    return d;
}
#define FULLM 0xFFFFFFFFu

// ---------------------------------------------------------------------------
__global__ __launch_bounds__(CT, 4)
void mega_kernel(const float* __restrict__ logits,
                 const float* __restrict__ pred_boxes,
                 const int*   __restrict__ tgt_labels,
                 const float* __restrict__ tgt_boxes,
                 float* __restrict__ out)
{
    extern __shared__ char dyn[];
    const int tid = threadIdx.x;
    const int bid = blockIdx.x;
    const int lane = tid & 31;
    const int wid = tid >> 5;
    const float4* tb4 = reinterpret_cast<const float4*>(tgt_boxes);

    __shared__ int s_tile;

    // ========= ROLE A: tracked columns (cols < 100) -> g_costT AND out ======
    if (bid < NB_A) {
        __shared__ float4 a_tb[T_];
        __shared__ int    a_tl[T_];
        if (tid < T_) { a_tb[tid] = tb4[tid]; a_tl[tid] = tgt_labels[tid]; }
        __syncthreads();

        const int gr = bid * CT + tid;          // global query row
        if (gr < BQ_) {
            float4 pb = reinterpret_cast<const float4*>(pred_boxes)[gr];
            const float pcx = pb.x, pcy = pb.y, pw = pb.z, ph = pb.w;
            const float px0 = pcx - 0.5f * pw, py0 = pcy - 0.5f * ph;
            const float px1 = pcx + 0.5f * pw, py1 = pcy + 0.5f * ph;
            const float pa  = (px1 - px0) * (py1 - py0);
            const int b    = gr / Q_;
            const int lrow = gr - b * Q_;
            const float* lrl = logits + (size_t)gr * C_;
            float* orow = out + (size_t)gr * BT_;   // thread-sequential j writes

            for (int j = 0; j < T_; j++) {
                float4 t = a_tb[j];
                float xx0 = t.x - 0.5f * t.z, yy0 = t.y - 0.5f * t.w;
                float xx1 = t.x + 0.5f * t.z, yy1 = t.y + 0.5f * t.w;
                float ta  = (xx1 - xx0) * (yy1 - yy0);
                float pr  = 1.0f / (1.0f + expf(-lrl[a_tl[j]]));

                float l1 = fabsf(pcx - t.x) + fabsf(pcy - t.y)
                         + fabsf(pw - t.z) + fabsf(ph - t.w);
                float ltx = fmaxf(px0, xx0), lty = fmaxf(py0, yy0);
                float rbx = fminf(px1, xx1), rby = fminf(py1, yy1);
                float inter = fmaxf(rbx - ltx, 0.0f) * fmaxf(rby - lty, 0.0f);
                float uni = pa + ta - inter;
                float iou = inter / uni;
                float ex0 = fminf(px0, xx0), ey0 = fminf(py0, yy0);
                float ex1 = fmaxf(px1, xx1), ey1 = fmaxf(py1, yy1);
                float earea = (ex1 - ex0) * (ey1 - ey0);
                float giou = iou - (earea - uni) / earea;
                float cv = l1 - pr - giou;
                g_costT[b][j][lrow] = cv;
                orow[j] = cv;                      // B-role skips j<100
            }
        }
        __threadfence();
        __syncthreads();
        if (tid == 0) atomicAdd(&g_ready, 1u);
        // fall through to work-stealing
    }
    // =================== ROLE G: greedy matcher =============================
    else if (bid < NB_A + NB_G) {
        const int b = bid - NB_A;
        while (*((volatile unsigned*)&g_ready) < NB_A) __nanosleep(200);
        __threadfence();

        __shared__ unsigned long long s_init[T_];
        for (int c = wid; c < T_; c += 8) {
            const float* colp = g_costT[b][c];
            unsigned long long best = ~0ull;
            for (int rr = lane; rr < Q_; rr += 32) {
                unsigned long long p =
                    ((unsigned long long)fkey(colp[rr]) << 32)
                    | (unsigned)((rr << 7) | c);
                if (p < best) best = p;
            }
            unsigned bk  = (unsigned)(best >> 32);
            unsigned mbk = redux_min_u32(bk);
            unsigned bt  = (bk == mbk) ? (unsigned)best : 0xFFFFFFFFu;
            unsigned mbt = redux_min_u32(bt);
            if (lane == 0)
                s_init[c] = ((unsigned long long)mbk << 32) | mbt;
        }
        __syncthreads();

        if (wid == 0) {
            unsigned long long slot[4];
            #pragma unroll
            for (int s = 0; s < 4; s++)
                slot[s] = (lane < 25) ? s_init[lane * 4 + s] : ~0ull;
            unsigned mrow = 0;

            float* ro = out + COST_ELEMS + b * T_;
            float* co = out + COST_ELEMS + B_ * T_ + b * T_;

            for (int step = 0; step < T_; step++) {
                unsigned long long m = slot[0];
                if (slot[1] < m) m = slot[1];
                if (slot[2] < m) m = slot[2];
                if (slot[3] < m) m = slot[3];

                unsigned k  = (unsigned)(m >> 32);
                unsigned mk = redux_min_u32(k);
                unsigned tag = (k == mk) ? (unsigned)m : 0xFFFFFFFFu;
                unsigned mt  = redux_min_u32(tag);

                const int r = (int)(mt >> 7);
                const int c = (int)(mt & 0x7Fu);

                if (lane == 0) { ro[step] = (float)r; co[step] = (float)c; }
                if (lane == (r & 31)) mrow |= 1u << (r >> 5);
                if (lane == (c >> 2)) slot[c & 3] = ~0ull;

                if (step == T_ - 1) break;

                bool n0 = ((int)((slot[0] >> 7) & 0x3FFu) == r);
                bool n1 = ((int)((slot[1] >> 7) & 0x3FFu) == r);
                bool n2 = ((int)((slot[2] >> 7) & 0x3FFu) == r);
                bool n3 = ((int)((slot[3] >> 7) & 0x3FFu) == r);
                unsigned any = __ballot_sync(FULLM, n0 | n1 | n2 | n3);
                if (any == 0) continue;

                #pragma unroll
                for (int s = 0; s < 4; s++) {
                    bool ns = (s == 0) ? n0 : (s == 1) ? n1 : (s == 2) ? n2 : n3;
                    unsigned need = __ballot_sync(FULLM, ns);
                    while (need) {
                        int ln = __ffs(need) - 1;
                        need &= need - 1;
                        int cc = __shfl_sync(FULLM, (int)(slot[s] & 0x7Fu), ln);
                        const float* colp = g_costT[b][cc];
                        unsigned long long best = ~0ull;
                        for (int i = 0, rr = lane; rr < Q_; i++, rr += 32) {
                            if (!((mrow >> i) & 1u)) {
                                unsigned long long p =
                                    ((unsigned long long)fkey(colp[rr]) << 32)
                                    | (unsigned)((rr << 7) | cc);
                                if (p < best) best = p;
                            }
                        }
                        unsigned bk  = (unsigned)(best >> 32);
                        unsigned mbk = redux_min_u32(bk);
                        unsigned bt  = (bk == mbk) ? (unsigned)best : 0xFFFFFFFFu;
                        unsigned mbt = redux_min_u32(bt);
                        if (lane == ln)
                            slot[s] = ((unsigned long long)mbk << 32) | mbt;
                    }
                }
            }

            if (lane == 0) {
                __threadfence();
                unsigned old = atomicAdd(&g_done, 1u);
                if (old == NB_G - 1) {
                    atomicExch(&g_ready, 0u);
                    atomicExch(&g_done, 0u);
                }
            }
        }
        __syncthreads();   // warps 1-7 rejoin warp 0 here
        // fall through to work-stealing
    }

    // ====== ALL CTAs: cost matrix cols [100,1600) via work-stealing =========
    {
        float4*        s_tb = (float4*)(dyn + OFF_TB);
        unsigned char* s_tl = (unsigned char*)(dyn + OFF_TL);
        float*         s_pr = (float*)(dyn + OFF_PR);   // [RPB][92]

        // stage targets ONCE per CTA
        for (int j = tid; j < BT_; j += CT) {
            s_tb[j] = tb4[j];
            s_tl[j] = (unsigned char)tgt_labels[j];
        }

        for (;;) {
            if (tid == 0) s_tile = (int)atomicAdd(&g_tile, 1u);
            __syncthreads();   // publishes s_tile; prior-tile s_pr readers done
            const int tile = s_tile;
            if (tile >= TILES) break;
            const int base_i = tile * RPB;

            for (int k = tid; k < RPB * C_; k += CT) {
                int rr = k / C_, c = k % C_;
                float xv = logits[(size_t)(base_i + rr) * C_ + c];
                s_pr[rr * 92 + c] = 1.0f / (1.0f + expf(-xv));
            }
            __syncthreads();

            float pcx[RPB], pcy[RPB], pw[RPB], ph[RPB];
            float px0[RPB], py0[RPB], px1[RPB], py1[RPB], pa[RPB];
            #pragma unroll
            for (int rr = 0; rr < RPB; rr++) {
                float4 pb = reinterpret_cast<const float4*>(pred_boxes)[base_i + rr];
                pcx[rr] = pb.x; pcy[rr] = pb.y; pw[rr] = pb.z; ph[rr] = pb.w;
                px0[rr] = pb.x - 0.5f * pb.z; py0[rr] = pb.y - 0.5f * pb.w;
                px1[rr] = pb.x + 0.5f * pb.z; py1[rr] = pb.y + 0.5f * pb.w;
                pa[rr]  = (px1[rr] - px0[rr]) * (py1[rr] - py0[rr]);
            }
            float* orow0 = out + (size_t)base_i * BT_;

            // cols < 100 are written by role A; start at 100
            for (int j = T_ + tid; j < BT_; j += CT) {
                float4 t = s_tb[j];
                int lb = s_tl[j];
                float xx0 = t.x - 0.5f * t.z, yy0 = t.y - 0.5f * t.w;
                float xx1 = t.x + 0.5f * t.z, yy1 = t.y + 0.5f * t.w;
                float ta  = (xx1 - xx0) * (yy1 - yy0);
                #pragma unroll
                for (int rr = 0; rr < RPB; rr++) {
                    float l1 = fabsf(pcx[rr] - t.x) + fabsf(pcy[rr] - t.y)
                             + fabsf(pw[rr] - t.z) + fabsf(ph[rr] - t.w);
                    float ltx = fmaxf(px0[rr], xx0), lty = fmaxf(py0[rr], yy0);
                    float rbx = fminf(px1[rr], xx1), rby = fminf(py1[rr], yy1);
                    float inter = fmaxf(rbx - ltx, 0.0f) * fmaxf(rby - lty, 0.0f);
                    float uni = pa[rr] + ta - inter;
                    float iou = inter / uni;
                    float ex0 = fminf(px0[rr], xx0), ey0 = fminf(py0[rr], yy0);
                    float ex1 = fmaxf(px1[rr], xx1), ey1 = fmaxf(py1[rr], yy1);
                    float earea = (ex1 - ex0) * (ey1 - ey0);
                    float giou = iou - (earea - uni) / earea;
                    orow0[(size_t)rr * BT_ + j] = l1 - s_pr[rr * 92 + lb] - giou;
                }
            }
        }

        // last CTA out resets the steal counter for the next graph replay
        if (tid == 0) {
            unsigned old = atomicAdd(&g_exit, 1u);
            if (old == GRID - 1) {
                atomicExch(&g_tile, 0u);
                atomicExch(&g_exit, 0u);
            }
        }
    }
}

// ---------------------------------------------------------------------------
extern "C" void kernel_launch(void* const* d_in, const int* in_sizes, int n_in,
                              void* d_out, int out_size)
{
    const float* logits     = (const float*)d_in[0];
    const float* pred_boxes = (const float*)d_in[1];
    const int*   tgt_labels = (const int*)  d_in[2];
    const float* tgt_boxes  = (const float*)d_in[3];
    float* out = (float*)d_out;

    cudaFuncSetAttribute(mega_kernel,
                         cudaFuncAttributeMaxDynamicSharedMemorySize, SMEM_DYN);

    mega_kernel<<<GRID, CT, SMEM_DYN>>>(
        logits, pred_boxes, tgt_labels, tgt_boxes, out);
}

// round 17
// speedup vs baseline: 1.0545x; 1.0545x over previous
#include <cuda_runtime.h>
#include <cstdint>

#define B_   16
#define Q_   900
#define C_   91
#define T_   100
#define BT_  1600
#define BQ_  14400
#define COST_ELEMS 23040000
#define RPB  4
#define CT   256
#define TILES (BQ_ / RPB)        // 3600

#define NB_A 57                  // tracked-column blocks (one row/thread)
#define NB_G 16                  // greedy blocks (one per batch)
#define NB_B 519                 // persistent cost blocks
#define GRID (NB_A + NB_G + NB_B)

// dynamic smem layout (B role)
#define OFF_TB 0                         // float4[1600] target cxcywh
#define OFF_TL 25600                     // uchar[1600] labels
#define OFF_PR 27232                     // float[RPB][92] sigmoid probs
#define SMEM_DYN (OFF_PR + RPB * 92 * 4) // ~28.7 KB

// Transposed tracked columns: g_costT[b][col][row]; fully overwritten by A
// every run (no init needed). Contiguous columns for greedy reads.
__device__ float g_costT[B_][T_][Q_];
__device__ unsigned g_ready;    // zero-init; self-reset by last greedy block
__device__ unsigned g_done;     // zero-init; self-reset by last greedy block

__device__ __forceinline__ unsigned fkey(float f) {
    unsigned b = __float_as_uint(f);
    return (b & 0x80000000u) ? ~b : (b | 0x80000000u);
}
__device__ __forceinline__ unsigned redux_min_u32(unsigned v) {
    unsigned d;
    asm("redux.sync.min.u32 %0, %1, 0xffffffff;" : "=r"(d) : "r"(v));
    return d;
}
#define FULLM 0xFFFFFFFFu

// ---------------------------------------------------------------------------
__global__ __launch_bounds__(CT, 4)
void mega_kernel(const float* __restrict__ logits,
                 const float* __restrict__ pred_boxes,
                 const int*   __restrict__ tgt_labels,
                 const float* __restrict__ tgt_boxes,
                 float* __restrict__ out)
{
    extern __shared__ char dyn[];
    const int tid = threadIdx.x;
    const int bid = blockIdx.x;
    const int lane = tid & 31;
    const int wid = tid >> 5;
    const float4* tb4 = reinterpret_cast<const float4*>(tgt_boxes);

    // ====== ROLE A: tracked columns (cols < 100), IEEE-exact (feeds match) ==
    if (bid < NB_A) {
        __shared__ float4 a_tb[T_];
        __shared__ int    a_tl[T_];
        if (tid < T_) { a_tb[tid] = tb4[tid]; a_tl[tid] = tgt_labels[tid]; }
        __syncthreads();

        const int gr = bid * CT + tid;          // global query row
        if (gr < BQ_) {
            float4 pb = reinterpret_cast<const float4*>(pred_boxes)[gr];
            const float pcx = pb.x, pcy = pb.y, pw = pb.z, ph = pb.w;
            const float px0 = pcx - 0.5f * pw, py0 = pcy - 0.5f * ph;
            const float px1 = pcx + 0.5f * pw, py1 = pcy + 0.5f * ph;
            const float pa  = (px1 - px0) * (py1 - py0);
            const int b    = gr / Q_;
            const int lrow = gr - b * Q_;
            const float* lrl = logits + (size_t)gr * C_;

            for (int j = 0; j < T_; j++) {
                float4 t = a_tb[j];
                float xx0 = t.x - 0.5f * t.z, yy0 = t.y - 0.5f * t.w;
                float xx1 = t.x + 0.5f * t.z, yy1 = t.y + 0.5f * t.w;
                float ta  = (xx1 - xx0) * (yy1 - yy0);
                float pr  = 1.0f / (1.0f + expf(-lrl[a_tl[j]]));

                float l1 = fabsf(pcx - t.x) + fabsf(pcy - t.y)
                         + fabsf(pw - t.z) + fabsf(ph - t.w);
                float ltx = fmaxf(px0, xx0), lty = fmaxf(py0, yy0);
                float rbx = fminf(px1, xx1), rby = fminf(py1, yy1);
                float inter = fmaxf(rbx - ltx, 0.0f) * fmaxf(rby - lty, 0.0f);
                float uni = pa + ta - inter;
                float iou = inter / uni;
                float ex0 = fminf(px0, xx0), ey0 = fminf(py0, yy0);
                float ex1 = fmaxf(px1, xx1), ey1 = fmaxf(py1, yy1);
                float earea = (ex1 - ex0) * (ey1 - ey0);
                float giou = iou - (earea - uni) / earea;
                g_costT[b][j][lrow] = l1 - pr - giou;
            }
        }
        __threadfence();
        __syncthreads();
        if (tid == 0) atomicAdd(&g_ready, 1u);
        return;
    }

    // =================== ROLE G: greedy matcher =============================
    if (bid < NB_A + NB_G) {
        const int b = bid - NB_A;
        while (*((volatile unsigned*)&g_ready) < NB_A) __nanosleep(200);
        __threadfence();

        __shared__ unsigned long long s_init[T_];
        for (int c = wid; c < T_; c += 8) {
            const float* colp = g_costT[b][c];
            unsigned long long best = ~0ull;
            for (int rr = lane; rr < Q_; rr += 32) {
                unsigned long long p =
                    ((unsigned long long)fkey(colp[rr]) << 32)
                    | (unsigned)((rr << 7) | c);
                if (p < best) best = p;
            }
            unsigned bk  = (unsigned)(best >> 32);
            unsigned mbk = redux_min_u32(bk);
            unsigned bt  = (bk == mbk) ? (unsigned)best : 0xFFFFFFFFu;
            unsigned mbt = redux_min_u32(bt);
            if (lane == 0)
                s_init[c] = ((unsigned long long)mbk << 32) | mbt;
        }
        __syncthreads();
        if (wid != 0) return;

        unsigned long long slot[4];
        #pragma unroll
        for (int s = 0; s < 4; s++)
            slot[s] = (lane < 25) ? s_init[lane * 4 + s] : ~0ull;
        unsigned mrow = 0;

        float* ro = out + COST_ELEMS + b * T_;
        float* co = out + COST_ELEMS + B_ * T_ + b * T_;

        for (int step = 0; step < T_; step++) {
            unsigned long long m = slot[0];
            if (slot[1] < m) m = slot[1];
            if (slot[2] < m) m = slot[2];
            if (slot[3] < m) m = slot[3];

            unsigned k  = (unsigned)(m >> 32);
            unsigned mk = redux_min_u32(k);
            unsigned tag = (k == mk) ? (unsigned)m : 0xFFFFFFFFu;
            unsigned mt  = redux_min_u32(tag);

            const int r = (int)(mt >> 7);
            const int c = (int)(mt & 0x7Fu);

            if (lane == 0) { ro[step] = (float)r; co[step] = (float)c; }
            if (lane == (r & 31)) mrow |= 1u << (r >> 5);
            if (lane == (c >> 2)) slot[c & 3] = ~0ull;

            if (step == T_ - 1) break;

            bool n0 = ((int)((slot[0] >> 7) & 0x3FFu) == r);
            bool n1 = ((int)((slot[1] >> 7) & 0x3FFu) == r);
            bool n2 = ((int)((slot[2] >> 7) & 0x3FFu) == r);
            bool n3 = ((int)((slot[3] >> 7) & 0x3FFu) == r);
            unsigned any = __ballot_sync(FULLM, n0 | n1 | n2 | n3);
            if (any == 0) continue;

            #pragma unroll
            for (int s = 0; s < 4; s++) {
                bool ns = (s == 0) ? n0 : (s == 1) ? n1 : (s == 2) ? n2 : n3;
                unsigned need = __ballot_sync(FULLM, ns);
                while (need) {
                    int ln = __ffs(need) - 1;
                    need &= need - 1;
                    int cc = __shfl_sync(FULLM, (int)(slot[s] & 0x7Fu), ln);
                    const float* colp = g_costT[b][cc];
                    unsigned long long best = ~0ull;
                    for (int i = 0, rr = lane; rr < Q_; i++, rr += 32) {
                        if (!((mrow >> i) & 1u)) {
                            unsigned long long p =
                                ((unsigned long long)fkey(colp[rr]) << 32)
                                | (unsigned)((rr << 7) | cc);
                            if (p < best) best = p;
                        }
                    }
                    unsigned bk  = (unsigned)(best >> 32);
                    unsigned mbk = redux_min_u32(bk);
                    unsigned bt  = (bk == mbk) ? (unsigned)best : 0xFFFFFFFFu;
                    unsigned mbt = redux_min_u32(bt);
                    if (lane == ln)
                        slot[s] = ((unsigned long long)mbk << 32) | mbt;
                }
            }
        }

        if (lane == 0) {
            __threadfence();
            unsigned old = atomicAdd(&g_done, 1u);
            if (old == NB_G - 1) {
                atomicExch(&g_ready, 0u);
                atomicExch(&g_done, 0u);
            }
        }
        return;
    }

    // ====== ROLE B: full cost matrix, persistent; __fdividef (value-only
    // precision, rel err ~3.5e-7 << 1e-3; never feeds the matching) =========
    {
        float4*        s_tb = (float4*)(dyn + OFF_TB);
        unsigned char* s_tl = (unsigned char*)(dyn + OFF_TL);
        float*         s_pr = (float*)(dyn + OFF_PR);   // [RPB][92]

        // stage targets ONCE per persistent block
        for (int j = tid; j < BT_; j += CT) {
            s_tb[j] = tb4[j];
            s_tl[j] = (unsigned char)tgt_labels[j];
        }

        for (int tile = bid - NB_A - NB_G; tile < TILES; tile += NB_B) {
            const int base_i = tile * RPB;
            __syncthreads();   // prior tile readers done (covers staging on iter 0)
            for (int k = tid; k < RPB * C_; k += CT) {
                int rr = k / C_, c = k % C_;
                float xv = logits[(size_t)(base_i + rr) * C_ + c];
                s_pr[rr * 92 + c] = 1.0f / (1.0f + expf(-xv));
            }
            __syncthreads();

            float pcx[RPB], pcy[RPB], pw[RPB], ph[RPB];
            float px0[RPB], py0[RPB], px1[RPB], py1[RPB], pa[RPB];
            #pragma unroll
            for (int rr = 0; rr < RPB; rr++) {
                float4 pb = reinterpret_cast<const float4*>(pred_boxes)[base_i + rr];
                pcx[rr] = pb.x; pcy[rr] = pb.y; pw[rr] = pb.z; ph[rr] = pb.w;
                px0[rr] = pb.x - 0.5f * pb.z; py0[rr] = pb.y - 0.5f * pb.w;
                px1[rr] = pb.x + 0.5f * pb.z; py1[rr] = pb.y + 0.5f * pb.w;
                pa[rr]  = (px1[rr] - px0[rr]) * (py1[rr] - py0[rr]);
            }
            float* orow0 = out + (size_t)base_i * BT_;

            for (int j = tid; j < BT_; j += CT) {
                float4 t = s_tb[j];
                int lb = s_tl[j];
                float xx0 = t.x - 0.5f * t.z, yy0 = t.y - 0.5f * t.w;
                float xx1 = t.x + 0.5f * t.z, yy1 = t.y + 0.5f * t.w;
                float ta  = (xx1 - xx0) * (yy1 - yy0);
                #pragma unroll
                for (int rr = 0; rr < RPB; rr++) {
                    float l1 = fabsf(pcx[rr] - t.x) + fabsf(pcy[rr] - t.y)
                             + fabsf(pw[rr] - t.z) + fabsf(ph[rr] - t.w);
                    float ltx = fmaxf(px0[rr], xx0), lty = fmaxf(py0[rr], yy0);
                    float rbx = fminf(px1[rr], xx1), rby = fminf(py1[rr], yy1);
                    float inter = fmaxf(rbx - ltx, 0.0f) * fmaxf(rby - lty, 0.0f);
                    float uni = pa[rr] + ta - inter;
                    float iou = __fdividef(inter, uni);
                    float ex0 = fminf(px0[rr], xx0), ey0 = fminf(py0[rr], yy0);
                    float ex1 = fmaxf(px1[rr], xx1), ey1 = fmaxf(py1[rr], yy1);
                    float earea = (ex1 - ex0) * (ey1 - ey0);
                    float giou = iou - __fdividef(earea - uni, earea);
                    orow0[(size_t)rr * BT_ + j] = l1 - s_pr[rr * 92 + lb] - giou;
                }
            }
        }
    }
}

// ---------------------------------------------------------------------------
extern "C" void kernel_launch(void* const* d_in, const int* in_sizes, int n_in,
                              void* d_out, int out_size)
{
    const float* logits     = (const float*)d_in[0];
    const float* pred_boxes = (const float*)d_in[1];
    const int*   tgt_labels = (const int*)  d_in[2];
    const float* tgt_boxes  = (const float*)d_in[3];
    float* out = (float*)d_out;

    cudaFuncSetAttribute(mega_kernel,
                         cudaFuncAttributeMaxDynamicSharedMemorySize, SMEM_DYN);

    mega_kernel<<<GRID, CT, SMEM_DYN>>>(
        logits, pred_boxes, tgt_labels, tgt_boxes, out);
}